// round 15
// baseline (speedup 1.0000x reference)
#include <cuda_runtime.h>
#include <cuda_fp16.h>
#include <cstdint>

#define BT 32768
#define NF 32
#define NU 64
#define EPS 1e-3f
#define W_OFF (BT * NU)

// ---- GRN-as-1D-function table (post-LN y values) ----
#define XMIN  (-6.0f)
#define NSEG  768
#define DX    0.015625f
#define INVDX 64.0f
#define NNODE 769

__device__ __align__(16) uint32_t g_tab[NF][NNODE][NU / 2];   // half2-packed y, ~3.15 MB

// ---------------- helpers ----------------
__device__ __forceinline__ uint32_t smem_u32(const void* p) {
    uint32_t a;
    asm("{ .reg .u64 t; cvta.to.shared.u64 t, %1; cvt.u32.u64 %0, t; }" : "=r"(a) : "l"(p));
    return a;
}
__device__ __forceinline__ float eluf(float z)  { return z > 0.f ? z : (__expf(z) - 1.f); }
__device__ __forceinline__ float sigmf(float z) {
    float t, h = 0.5f * z;
    asm("tanh.approx.f32 %0, %1;" : "=f"(t) : "f"(h));
    return fmaf(0.5f, t, 0.5f);
}
__device__ __forceinline__ uint32_t packh2(float lo, float hi) {
    __half2 h = __floats2half2_rn(lo, hi);
    return *reinterpret_cast<uint32_t*>(&h);
}
__device__ __forceinline__ float2 unpackh2(uint32_t u) {
    __half2 h = *reinterpret_cast<__half2*>(&u);
    return __half22float2(h);
}
__device__ __forceinline__ void mma16(float* c, const uint32_t* a, uint32_t b0, uint32_t b1) {
    asm volatile(
        "mma.sync.aligned.m16n8k16.row.col.f32.f16.f16.f32 "
        "{%0,%1,%2,%3}, {%4,%5,%6,%7}, {%8,%9}, {%0,%1,%2,%3};"
        : "+f"(c[0]), "+f"(c[1]), "+f"(c[2]), "+f"(c[3])
        : "r"(a[0]), "r"(a[1]), "r"(a[2]), "r"(a[3]), "r"(b0), "r"(b1));
}
__device__ __forceinline__ void ldsm4(uint32_t* r, uint32_t addr) {
    asm volatile("ldmatrix.sync.aligned.m8n8.x4.shared.b16 {%0,%1,%2,%3}, [%4];"
        : "=r"(r[0]), "=r"(r[1]), "=r"(r[2]), "=r"(r[3]) : "r"(addr));
}

// ============================================================================
// Kernel 1: k_tab — self-contained: builds fp16 weight image + folded biases
// in smem, evaluates per-feature GRN at table nodes via HMMA, applies LN,
// stores post-LN y as half2-packed rows.  Grid 7 x 32, 256 threads.
// smem: W2' fp16[64][72] (9216 B) | Wg' fp16[128][72] (18432 B) | vec f32[8][64]
//       then 8 x h2-tile [16][72] halves (2304 B each; also reused as fold scratch)
// ============================================================================
#define OFF_WG_B   9216
#define OFF_VEC_B  27648
#define KT_H2_OFF  29696u
#define KT_SMEM    48128u

__global__ __launch_bounds__(256) void k_tab(
    const float* __restrict__ W2, const float* __restrict__ Wg1, const float* __restrict__ Wg2,
    const float* __restrict__ b2, const float* __restrict__ bg1, const float* __restrict__ bg2,
    const float* __restrict__ W1, const float* __restrict__ b1,
    const float* __restrict__ Wp, const float* __restrict__ bp,
    const float* __restrict__ gamma, const float* __restrict__ beta)
{
    extern __shared__ char smem[];
    const uint32_t sbase = smem_u32(smem);

    const int f    = blockIdx.y;
    const int part = blockIdx.x;
    const int tid  = threadIdx.x;
    const int lane = tid & 31;
    const int warp = tid >> 5;
    const int q    = lane & 3;
    const int g    = lane >> 2;
    const int lrow = lane & 7;
    const int lmat = lane >> 3;
    const int nodeb = part * 128 + warp * 16;

    const float* W2f  = W2  + (size_t)f * 4096;
    const float* Wg1f = Wg1 + (size_t)f * 4096;
    const float* Wg2f = Wg2 + (size_t)f * 4096;

    __half* W2h = (__half*)smem;
    __half* Wgh = (__half*)(smem + OFF_WG_B);
    float*  vec = (float*)(smem + OFF_VEC_B);
    float*  scratch = (float*)(smem + KT_H2_OFF);   // fold partials (reused later)

    // ---- build fp16 images directly from global weights ----
    for (int i = tid; i < 4096; i += 256) {
        int n = i >> 6, k = i & 63;
        W2h[n * 72 + k] = __float2half_rn(W2f[k * 64 + n]);
    }
    for (int i = tid; i < 8192; i += 256) {
        int n = i >> 6, k = i & 63;
        float v = (n < 64) ? Wg1f[k * 64 + n] : Wg2f[k * 64 + (n - 64)];
        Wgh[n * 72 + k] = __float2half_rn(v);
    }
    if (tid < 64) {
        int o = f * 64 + tid;
        vec[0   + tid] = W1[o];
        vec[64  + tid] = b1[o];
        vec[128 + tid] = Wp[o];
        vec[192 + tid] = bp[o];
        vec[256 + tid] = gamma[o];
        vec[320 + tid] = beta[o];
        scratch[512 + tid] = b2[o];     // b2 staging
    }
    __syncthreads();

    // ---- parallel bias fold: be = bg + b2 @ Wg  (2-way k-split per output) ----
    {
        const int o    = tid & 127;     // 0..63 -> be1, 64..127 -> be2
        const int half = tid >> 7;      // k-chunk
        const int oo   = o & 63;
        const float* Wsrc = (o < 64) ? Wg1f : Wg2f;
        float s = 0.f;
        #pragma unroll 8
        for (int u = half * 32; u < half * 32 + 32; u++)
            s += scratch[512 + u] * Wsrc[u * 64 + oo];
        scratch[tid] = s;
    }
    __syncthreads();
    if (tid < 128) {
        float tot = scratch[tid] + scratch[tid + 128];
        int oo = tid & 63;
        if (tid < 64) vec[384 + oo] = bg1[f * 64 + oo] + tot;
        else          vec[448 + oo] = bg2[f * 64 + oo] + tot;
    }
    __syncthreads();

    // ---- HMMA evaluation at this CTA's nodes ----
    uint32_t* h2u = (uint32_t*)(smem + KT_H2_OFF) + warp * 576;
    const uint32_t h2a = sbase + KT_H2_OFF + warp * 2304;
    const uint32_t bwa  = sbase;
    const uint32_t wgwa = sbase + OFF_WG_B;
    const float*   vecf = vec;

    float xf[2];
    int   node[2];
    #pragma unroll
    for (int t = 0; t < 2; t++) {
        node[t] = nodeb + g + 8 * t;
        xf[t] = XMIN + (float)node[t] * DX;
    }

    uint32_t a1[4][4];
    #pragma unroll
    for (int s = 0; s < 4; s++) {
        #pragma unroll
        for (int p = 0; p < 2; p++) {
            int u0 = 16 * s + 2 * q + 8 * p;
            float2 wv  = *(const float2*)&vecf[u0];
            float2 bv2 = *(const float2*)&vecf[64 + u0];
            a1[s][2*p]   = packh2(eluf(fmaf(xf[0], wv.x, bv2.x)), eluf(fmaf(xf[0], wv.y, bv2.y)));
            a1[s][2*p+1] = packh2(eluf(fmaf(xf[1], wv.x, bv2.x)), eluf(fmaf(xf[1], wv.y, bv2.y)));
        }
    }

    #pragma unroll
    for (int j = 0; j < 8; j++) {
        uint32_t ad = bwa + (uint32_t)(((8 * j + lrow) * 36 + 4 * lmat) * 4);
        uint32_t bb[8];
        ldsm4(bb, ad);
        ldsm4(bb + 4, ad + 64);
        float c0[4] = {0.f,0.f,0.f,0.f};
        mma16(c0, a1[0], bb[0], bb[1]);
        mma16(c0, a1[1], bb[2], bb[3]);
        mma16(c0, a1[2], bb[4], bb[5]);
        mma16(c0, a1[3], bb[6], bb[7]);
        int cw = 4 * j + q;
        h2u[(g    ) * 36 + cw] = packh2(c0[0], c0[1]);
        h2u[(g + 8) * 36 + cw] = packh2(c0[2], c0[3]);
    }
    __syncwarp();

    uint32_t a2[4][4];
    {
        uint32_t abase = h2a + (uint32_t)((((lmat & 1) * 8 + lrow) * 36 + (lmat >> 1) * 4) * 4);
        #pragma unroll
        for (int s = 0; s < 4; s++)
            ldsm4(a2[s], abase + (uint32_t)(32 * s));
    }

    float sv[2][16];
    float ssum[2] = {0.f, 0.f};
    float ssq[2]  = {0.f, 0.f};
    #pragma unroll 2
    for (int j = 0; j < 8; j++) {
        uint32_t ad1 = wgwa + (uint32_t)(((8 * j + lrow) * 36 + 4 * lmat) * 4);
        uint32_t bb1[8], bb2[8];
        ldsm4(bb1, ad1);
        ldsm4(bb1 + 4, ad1 + 64);
        ldsm4(bb2, ad1 + 9216);
        ldsm4(bb2 + 4, ad1 + 9216 + 64);
        float c1[4] = {0.f,0.f,0.f,0.f};
        float c2[4] = {0.f,0.f,0.f,0.f};
        #pragma unroll
        for (int s = 0; s < 4; s++) {
            mma16(c1, a2[s], bb1[2*s], bb1[2*s+1]);
            mma16(c2, a2[s], bb2[2*s], bb2[2*s+1]);
        }
        int col0 = 8 * j + 2 * q;
        float2 be1v = *(const float2*)&vecf[384 + col0];
        float2 be2v = *(const float2*)&vecf[448 + col0];
        float2 wpv  = *(const float2*)&vecf[128 + col0];
        float2 bpv  = *(const float2*)&vecf[192 + col0];
        #pragma unroll
        for (int t = 0; t < 2; t++) {
            float o1a = c1[2*t]     + be1v.x;
            float o1b = c1[2*t + 1] + be1v.y;
            float o2a = c2[2*t]     + be2v.x;
            float o2b = c2[2*t + 1] + be2v.y;
            float sv0 = fmaf(o1a, sigmf(o2a), fmaf(xf[t], wpv.x, bpv.x));
            float sv1 = fmaf(o1b, sigmf(o2b), fmaf(xf[t], wpv.y, bpv.y));
            sv[t][2*j]     = sv0;
            sv[t][2*j + 1] = sv1;
            ssum[t] += sv0 + sv1;
            ssq[t]  = fmaf(sv0, sv0, fmaf(sv1, sv1, ssq[t]));
        }
    }

    #pragma unroll
    for (int off = 1; off < 4; off <<= 1) {
        #pragma unroll
        for (int t = 0; t < 2; t++) {
            ssum[t] += __shfl_xor_sync(0xffffffffu, ssum[t], off);
            ssq[t]  += __shfl_xor_sync(0xffffffffu, ssq[t],  off);
        }
    }

    #pragma unroll
    for (int t = 0; t < 2; t++) {
        float mean = ssum[t] * (1.f / 64.f);
        float var  = ssq[t] * (1.f / 64.f) - mean * mean;
        float inv  = rsqrtf(var + EPS);
        if (node[t] < NNODE) {
            #pragma unroll
            for (int j = 0; j < 8; j++) {
                int col0 = 8 * j + 2 * q;
                float2 gv = *(const float2*)&vecf[256 + col0];
                float2 bv = *(const float2*)&vecf[320 + col0];
                float y0 = fmaf((sv[t][2*j]     - mean) * inv, gv.x, bv.x);
                float y1 = fmaf((sv[t][2*j + 1] - mean) * inv, gv.y, bv.y);
                g_tab[f][node[t]][4 * j + q] = packh2(y0, y1);
            }
        }
    }
}

// ============================================================================
// Kernel 2: k_fused — phase 1: warps 0-3 compute w (HMMA GRN over F) for the
// CTA's 64 tokens -> smem + global; phase 2: all 256 threads (4/token) do the
// table lerp-accumulate.  Grid 512 x 256 threads.
// ============================================================================
#define KF_W1   0u
#define KF_W2   2560u
#define KF_WG   5120u        // [64][40] halves
#define KF_HT   10240u       // 4 warps x [16][40] halves (1280 B each)
#define KF_XT   15360u       // x f32 [64][36]
#define KF_PRM  24576u       // 6 x 32 f32
#define KF_WS   25344u       // w f32 [64][36]
#define KF_SMEM 34560u

__global__ __launch_bounds__(256) void k_fused(
    const float* __restrict__ x,
    const float* __restrict__ w1w, const float* __restrict__ b1w,
    const float* __restrict__ w2w, const float* __restrict__ b2w,
    const float* __restrict__ wg1w, const float* __restrict__ bg1w,
    const float* __restrict__ wg2w, const float* __restrict__ bg2w,
    const float* __restrict__ gammaw, const float* __restrict__ betaw,
    float* __restrict__ wout,
    float* __restrict__ out)
{
    extern __shared__ char smw[];
    __half* w1h = (__half*)(smw + KF_W1);
    __half* w2h = (__half*)(smw + KF_W2);
    __half* wgh = (__half*)(smw + KF_WG);
    float*  xt  = (float*)(smw + KF_XT);
    float*  prm = (float*)(smw + KF_PRM);
    float*  ws  = (float*)(smw + KF_WS);
    const uint32_t sb = smem_u32(smw);

    const int tid  = threadIdx.x;
    const int lane = tid & 31;
    const int warp = tid >> 5;
    const int q    = lane & 3;
    const int g    = lane >> 2;
    const int lrow = lane & 7;
    const int lmat = lane >> 3;
    const size_t blk = (size_t)blockIdx.x * 64;

    for (int i = tid; i < 1024; i += 256) {
        int n = i >> 5, k = i & 31;
        w1h[n * 40 + k] = __float2half_rn(w1w[k * 32 + n]);
        w2h[n * 40 + k] = __float2half_rn(w2w[k * 32 + n]);
    }
    for (int i = tid; i < 2048; i += 256) {
        int n = i >> 5, k = i & 31;
        float v = (n < 32) ? wg1w[k * 32 + n] : wg2w[k * 32 + (n - 32)];
        wgh[n * 40 + k] = __float2half_rn(v);
    }
    if (tid < 32) {
        prm[tid]       = b1w[tid];
        prm[32 + tid]  = b2w[tid];
        prm[64 + tid]  = bg1w[tid];
        prm[96 + tid]  = bg2w[tid];
        prm[128 + tid] = gammaw[tid];
        prm[160 + tid] = betaw[tid];
    }
    {   // x [64][36] f32
        const int row = tid >> 2, off = (tid & 3) * 8;
        const float4* xp = (const float4*)(x + (blk + row) * 32 + off);
        float4* xr = (float4*)&xt[row * 36 + off];
        xr[0] = xp[0]; xr[1] = xp[1];
    }
    __syncthreads();

    // ---- phase 1: warps 0-3 compute w for 64 tokens ----
    if (warp < 4) {
        const int wtok = warp * 16;
        uint32_t* h2u = (uint32_t*)(smw + KF_HT) + warp * 320;
        const uint32_t htb = sb + KF_HT + (uint32_t)warp * 1280u;
        const uint32_t abw = htb + (uint32_t)((((lmat & 1) * 8 + lrow) * 20 + (lmat >> 1) * 4) * 4);

        const float* xr0 = &xt[(wtok + g) * 36];
        const float* xr1 = &xt[(wtok + g + 8) * 36];

        uint32_t a1[2][4];
        #pragma unroll
        for (int s = 0; s < 2; s++) {
            int k0 = 16 * s + 2 * q;
            a1[s][0] = packh2(xr0[k0],     xr0[k0 + 1]);
            a1[s][1] = packh2(xr1[k0],     xr1[k0 + 1]);
            a1[s][2] = packh2(xr0[k0 + 8], xr0[k0 + 9]);
            a1[s][3] = packh2(xr1[k0 + 8], xr1[k0 + 9]);
        }

        #pragma unroll
        for (int j = 0; j < 4; j++) {
            uint32_t ad = sb + KF_W1 + (uint32_t)(((8 * j + lrow) * 20 + 4 * lmat) * 4);
            uint32_t bb[4];
            ldsm4(bb, ad);
            float c[4] = {0.f, 0.f, 0.f, 0.f};
            mma16(c, a1[0], bb[0], bb[1]);
            mma16(c, a1[1], bb[2], bb[3]);
            int col0 = 8 * j + 2 * q;
            float b0 = prm[col0], b1v = prm[col0 + 1];
            h2u[g * 20 + 4 * j + q]       = packh2(eluf(c[0] + b0), eluf(c[1] + b1v));
            h2u[(g + 8) * 20 + 4 * j + q] = packh2(eluf(c[2] + b0), eluf(c[3] + b1v));
        }
        __syncwarp();
        uint32_t a2[2][4];
        ldsm4(a2[0], abw);
        ldsm4(a2[1], abw + 32);
        __syncwarp();

        #pragma unroll
        for (int j = 0; j < 4; j++) {
            uint32_t ad = sb + KF_W2 + (uint32_t)(((8 * j + lrow) * 20 + 4 * lmat) * 4);
            uint32_t bb[4];
            ldsm4(bb, ad);
            float c[4] = {0.f, 0.f, 0.f, 0.f};
            mma16(c, a2[0], bb[0], bb[1]);
            mma16(c, a2[1], bb[2], bb[3]);
            int col0 = 8 * j + 2 * q;
            float b0 = prm[32 + col0], b1v = prm[32 + col0 + 1];
            h2u[g * 20 + 4 * j + q]       = packh2(c[0] + b0, c[1] + b1v);
            h2u[(g + 8) * 20 + 4 * j + q] = packh2(c[2] + b0, c[3] + b1v);
        }
        __syncwarp();
        uint32_t a3[2][4];
        ldsm4(a3[0], abw);
        ldsm4(a3[1], abw + 32);

        float o1v[2][8], o2v[2][8];
        #pragma unroll
        for (int j = 0; j < 8; j++) {
            uint32_t ad = sb + KF_WG + (uint32_t)(((8 * j + lrow) * 20 + 4 * lmat) * 4);
            uint32_t bb[4];
            ldsm4(bb, ad);
            float c[4] = {0.f, 0.f, 0.f, 0.f};
            mma16(c, a3[0], bb[0], bb[1]);
            mma16(c, a3[1], bb[2], bb[3]);
            if (j < 4) {
                o1v[0][2*j] = c[0]; o1v[0][2*j+1] = c[1];
                o1v[1][2*j] = c[2]; o1v[1][2*j+1] = c[3];
            } else {
                int jj = j - 4;
                o2v[0][2*jj] = c[0]; o2v[0][2*jj+1] = c[1];
                o2v[1][2*jj] = c[2]; o2v[1][2*jj+1] = c[3];
            }
        }

        float s[2][8];
        float ssum[2] = {0.f, 0.f}, ssq[2] = {0.f, 0.f};
        #pragma unroll
        for (int t = 0; t < 2; t++) {
            const float* xr = (t == 0) ? xr0 : xr1;
            #pragma unroll
            for (int j = 0; j < 4; j++) {
                #pragma unroll
                for (int i2 = 0; i2 < 2; i2++) {
                    int col = 8 * j + 2 * q + i2;
                    float o1 = o1v[t][2*j + i2] + prm[64 + col];
                    float o2 = o2v[t][2*j + i2] + prm[96 + col];
                    float sv = fmaf(o1, sigmf(o2), xr[col]);
                    s[t][2*j + i2] = sv;
                    ssum[t] += sv;
                    ssq[t] = fmaf(sv, sv, ssq[t]);
                }
            }
        }
        #pragma unroll
        for (int off = 1; off < 4; off <<= 1) {
            #pragma unroll
            for (int t = 0; t < 2; t++) {
                ssum[t] += __shfl_xor_sync(0xffffffffu, ssum[t], off);
                ssq[t]  += __shfl_xor_sync(0xffffffffu, ssq[t],  off);
            }
        }
        #pragma unroll
        for (int t = 0; t < 2; t++) {
            float mean = ssum[t] * (1.f / 32.f);
            float var  = ssq[t] * (1.f / 32.f) - mean * mean;
            float inv  = rsqrtf(var + EPS);
            float y[8], mx = -1e30f;
            #pragma unroll
            for (int j = 0; j < 4; j++) {
                #pragma unroll
                for (int i2 = 0; i2 < 2; i2++) {
                    int col = 8 * j + 2 * q + i2;
                    float v = fmaf((s[t][2*j + i2] - mean) * inv, prm[128 + col], prm[160 + col]);
                    y[2*j + i2] = v;
                    mx = fmaxf(mx, v);
                }
            }
            #pragma unroll
            for (int off = 1; off < 4; off <<= 1)
                mx = fmaxf(mx, __shfl_xor_sync(0xffffffffu, mx, off));
            float se = 0.f;
            #pragma unroll
            for (int e = 0; e < 8; e++) { float ev = __expf(y[e] - mx); y[e] = ev; se += ev; }
            #pragma unroll
            for (int off = 1; off < 4; off <<= 1)
                se += __shfl_xor_sync(0xffffffffu, se, off);
            float r = 1.f / se;
            int row = wtok + g + 8 * t;
            float* orow = wout + (blk + row) * (size_t)NF;
            #pragma unroll
            for (int j = 0; j < 4; j++) {
                float2 v2 = make_float2(y[2*j] * r, y[2*j + 1] * r);
                *(float2*)&orow[8 * j + 2 * q] = v2;
                *(float2*)&ws[row * 36 + 8 * j + 2 * q] = v2;
            }
        }
    }
    __syncthreads();

    // ---- phase 2: table lerp-accumulate (4 threads/token) ----
    const int tok = tid >> 2;
    const int ql  = tid & 3;
    const int gb  = ql * 16;

    float acc[16];
    #pragma unroll
    for (int c = 0; c < 16; c++) acc[c] = 0.f;

    #pragma unroll 2
    for (int f = 0; f < NF; f++) {
        float xf = xt[tok * 36 + f];
        float wf = ws[tok * 36 + f];

        float tpos = (xf - XMIN) * INVDX;
        int   i    = (int)tpos;
        i = (i < 0) ? 0 : ((i > NSEG - 1) ? NSEG - 1 : i);
        float fr  = tpos - (float)i;
        float wfr = wf * fr;
        float wfa = wf - wfr;

        const uint4* r0 = (const uint4*)&g_tab[f][i][ql * 8];
        const uint4* r1 = (const uint4*)&g_tab[f][i + 1][ql * 8];
        uint4 a0 = r0[0], a1v = r0[1];
        uint4 b0 = r1[0], b1v = r1[1];

        const uint32_t aw[8] = { a0.x, a0.y, a0.z, a0.w, a1v.x, a1v.y, a1v.z, a1v.w };
        const uint32_t bw[8] = { b0.x, b0.y, b0.z, b0.w, b1v.x, b1v.y, b1v.z, b1v.w };
        #pragma unroll
        for (int c = 0; c < 8; c++) {
            float2 av = unpackh2(aw[c]);
            float2 bv = unpackh2(bw[c]);
            acc[2*c]   = fmaf(av.x, wfa, fmaf(bv.x, wfr, acc[2*c]));
            acc[2*c+1] = fmaf(av.y, wfa, fmaf(bv.y, wfr, acc[2*c+1]));
        }
    }

    {
        float4* op = (float4*)(out + (blk + tok) * NU + gb);
        #pragma unroll
        for (int c = 0; c < 4; c++)
            op[c] = make_float4(acc[4*c], acc[4*c+1], acc[4*c+2], acc[4*c+3]);
    }
}

// ============================================================================
extern "C" void kernel_launch(void* const* d_in, const int* in_sizes, int n_in,
                              void* d_out, int out_size) {
    const float* x    = (const float*)d_in[0];
    const float* W1   = (const float*)d_in[1];
    const float* b1   = (const float*)d_in[2];
    const float* W2   = (const float*)d_in[3];
    const float* b2   = (const float*)d_in[4];
    const float* Wg1  = (const float*)d_in[5];
    const float* bg1  = (const float*)d_in[6];
    const float* Wg2  = (const float*)d_in[7];
    const float* bg2  = (const float*)d_in[8];
    const float* Wp   = (const float*)d_in[9];
    const float* bp   = (const float*)d_in[10];
    const float* gamma= (const float*)d_in[11];
    const float* beta = (const float*)d_in[12];
    const float* w1w  = (const float*)d_in[13];
    const float* b1w  = (const float*)d_in[14];
    const float* w2w  = (const float*)d_in[15];
    const float* b2w  = (const float*)d_in[16];
    const float* wg1w = (const float*)d_in[17];
    const float* bg1w = (const float*)d_in[18];
    const float* wg2w = (const float*)d_in[19];
    const float* bg2w = (const float*)d_in[20];
    const float* gammaw = (const float*)d_in[21];
    const float* betaw  = (const float*)d_in[22];

    float* outp = (float*)d_out;
    float* wp   = outp + W_OFF;

    cudaFuncSetAttribute(k_tab, cudaFuncAttributeMaxDynamicSharedMemorySize, KT_SMEM);
    k_tab<<<dim3(7, 32), 256, KT_SMEM>>>(
        W2, Wg1, Wg2, b2, bg1, bg2, W1, b1, Wp, bp, gamma, beta);

    cudaFuncSetAttribute(k_fused, cudaFuncAttributeMaxDynamicSharedMemorySize, KF_SMEM);
    k_fused<<<BT / 64, 256, KF_SMEM>>>(
        x, w1w, b1w, w2w, b2w, wg1w, bg1w, wg2w, bg2w, gammaw, betaw, wp, outp);
}

// round 16
// speedup vs baseline: 1.0845x; 1.0845x over previous
#include <cuda_runtime.h>
#include <cuda_fp16.h>
#include <cstdint>

#define BT 32768
#define NF 32
#define NU 64
#define EPS 1e-3f
#define W_OFF (BT * NU)

// ---- GRN-as-1D-function table (post-LN y values) ----
#define XMIN  (-6.0f)
#define NSEG  768
#define DX    0.015625f
#define INVDX 64.0f
#define NNODE 769

// per-feature image (bytes): W2' fp16[64][72] | Wg' fp16[128][72] | vec f32[8][64]
#define IMG_BYTES  29696
#define OFF_WG_B   9216
#define OFF_VEC_B  27648

__device__ __align__(16) unsigned char g_img[NF][IMG_BYTES];
__device__ __align__(16) uint32_t g_tab[NF][NNODE][NU / 2];   // half2-packed y, ~3.15 MB

// ---------------- helpers ----------------
__device__ __forceinline__ uint32_t smem_u32(const void* p) {
    uint32_t a;
    asm("{ .reg .u64 t; cvta.to.shared.u64 t, %1; cvt.u32.u64 %0, t; }" : "=r"(a) : "l"(p));
    return a;
}
__device__ __forceinline__ float eluf(float z)  { return z > 0.f ? z : (__expf(z) - 1.f); }
__device__ __forceinline__ float sigmf(float z) {
    float t, h = 0.5f * z;
    asm("tanh.approx.f32 %0, %1;" : "=f"(t) : "f"(h));
    return fmaf(0.5f, t, 0.5f);
}
__device__ __forceinline__ uint32_t packh2(float lo, float hi) {
    __half2 h = __floats2half2_rn(lo, hi);
    return *reinterpret_cast<uint32_t*>(&h);
}
__device__ __forceinline__ float2 unpackh2(uint32_t u) {
    __half2 h = *reinterpret_cast<__half2*>(&u);
    return __half22float2(h);
}
__device__ __forceinline__ void mma16(float* c, const uint32_t* a, uint32_t b0, uint32_t b1) {
    asm volatile(
        "mma.sync.aligned.m16n8k16.row.col.f32.f16.f16.f32 "
        "{%0,%1,%2,%3}, {%4,%5,%6,%7}, {%8,%9}, {%0,%1,%2,%3};"
        : "+f"(c[0]), "+f"(c[1]), "+f"(c[2]), "+f"(c[3])
        : "r"(a[0]), "r"(a[1]), "r"(a[2]), "r"(a[3]), "r"(b0), "r"(b1));
}
__device__ __forceinline__ void ldsm4(uint32_t* r, uint32_t addr) {
    asm volatile("ldmatrix.sync.aligned.m8n8.x4.shared.b16 {%0,%1,%2,%3}, [%4];"
        : "=r"(r[0]), "=r"(r[1]), "=r"(r[2]), "=r"(r[3]) : "r"(addr));
}

#define MBARRIER_INIT(addr, cnt) \
    asm volatile("mbarrier.init.shared.b64 [%0], %1;" :: "r"(addr), "r"(cnt) : "memory")
#define MBARRIER_EXPECT_TX(addr, tx) \
    asm volatile("mbarrier.arrive.expect_tx.shared.b64 _, [%0], %1;" :: "r"(addr), "r"(tx) : "memory")
#define MBARRIER_WAIT_PARITY(addr, par) do { \
    uint32_t _m = (addr); uint32_t _p = (par); uint32_t _d; \
    asm volatile("{ .reg .pred p; mbarrier.try_wait.parity.acquire.cta.shared::cta.b64 p, [%1], %2; selp.b32 %0, 1, 0, p; }" \
        : "=r"(_d) : "r"(_m), "r"(_p) : "memory"); \
    if (!_d) { \
        asm volatile("{ .reg .pred P1; WL_%=: mbarrier.try_wait.parity.acquire.cta.shared::cta.b64 P1, [%0], %1, 0x989680; @P1 bra.uni WD_%=; bra.uni WL_%=; WD_%=: }" \
            :: "r"(_m), "r"(_p) : "memory"); \
    } } while (0)

__device__ __forceinline__ void bulk_g2s(uint32_t dst, const void* src, uint32_t bytes, uint32_t mbar) {
    asm volatile("cp.async.bulk.shared::cluster.global.mbarrier::complete_tx::bytes [%0], [%1], %2, [%3];"
                 :: "r"(dst), "l"(src), "r"(bytes), "r"(mbar) : "memory");
}

// ============================================================================
// Kernel 1: prep — per-feature fp16 images + PARALLEL folded gate biases.
// One feature per CTA, 256 threads.
// ============================================================================
__global__ __launch_bounds__(256) void k_prep(
    const float* __restrict__ W2, const float* __restrict__ Wg1, const float* __restrict__ Wg2,
    const float* __restrict__ b2, const float* __restrict__ bg1, const float* __restrict__ bg2,
    const float* __restrict__ W1, const float* __restrict__ b1,
    const float* __restrict__ Wp, const float* __restrict__ bp,
    const float* __restrict__ gamma, const float* __restrict__ beta)
{
    __shared__ float b2s[64];
    __shared__ float scr[256];

    const int f = blockIdx.x;
    const int tid = threadIdx.x;
    const float* W2f  = W2  + (size_t)f * 4096;
    const float* Wg1f = Wg1 + (size_t)f * 4096;
    const float* Wg2f = Wg2 + (size_t)f * 4096;
    unsigned char* img = g_img[f];
    __half* W2h = (__half*)img;
    __half* Wgh = (__half*)(img + OFF_WG_B);
    float*  vec = (float*)(img + OFF_VEC_B);

    if (tid < 64) b2s[tid] = b2[f * 64 + tid];

    for (int i = tid; i < 4096; i += 256) {
        int n = i >> 6, k = i & 63;
        W2h[n * 72 + k] = __float2half_rn(W2f[k * 64 + n]);
    }
    for (int i = tid; i < 8192; i += 256) {
        int n = i >> 6, k = i & 63;
        float v = (n < 64) ? Wg1f[k * 64 + n] : Wg2f[k * 64 + (n - 64)];
        Wgh[n * 72 + k] = __float2half_rn(v);
    }
    if (tid < 64) {
        int o = f * 64 + tid;
        vec[0   + tid] = W1[o];
        vec[64  + tid] = b1[o];
        vec[128 + tid] = Wp[o];
        vec[192 + tid] = bp[o];
        vec[256 + tid] = gamma[o];
        vec[320 + tid] = beta[o];
    }
    __syncthreads();

    // parallel fold: be = bg + b2 @ Wg (128 outputs x 2-way k-split)
    {
        const int o    = tid & 127;     // 0..63 -> be1, 64..127 -> be2
        const int half = tid >> 7;
        const int oo   = o & 63;
        const float* Wsrc = (o < 64) ? Wg1f : Wg2f;
        float s = 0.f;
        #pragma unroll 8
        for (int u = half * 32; u < half * 32 + 32; u++)
            s = fmaf(b2s[u], Wsrc[u * 64 + oo], s);
        scr[tid] = s;
    }
    __syncthreads();
    if (tid < 128) {
        float tot = scr[tid] + scr[tid + 128];
        int oo = tid & 63;
        if (tid < 64) vec[384 + oo] = bg1[f * 64 + oo] + tot;
        else          vec[448 + oo] = bg2[f * 64 + oo] + tot;
    }
}

// ============================================================================
// Kernel 2: k_tab — per-feature GRN at table nodes via HMMA + LN -> fp16 y rows.
// Grid 7 x 32, 256 threads = 8 warps x 16 nodes.  (R14 version)
// ============================================================================
#define KT_H2_OFF   29696u
#define KT_MBAR_OFF 48128u
#define KT_SMEM     48144u

__global__ __launch_bounds__(256) void k_tab()
{
    extern __shared__ char smem[];
    const uint32_t sbase = smem_u32(smem);

    const int f    = blockIdx.y;
    const int part = blockIdx.x;
    const int tid  = threadIdx.x;
    const int lane = tid & 31;
    const int warp = tid >> 5;
    const int q    = lane & 3;
    const int g    = lane >> 2;
    const int lrow = lane & 7;
    const int lmat = lane >> 3;
    const int nodeb = part * 128 + warp * 16;

    uint32_t* h2u = (uint32_t*)(smem + KT_H2_OFF) + warp * 576;
    const uint32_t h2a = sbase + KT_H2_OFF + warp * 2304;
    const uint32_t mbar = sbase + KT_MBAR_OFF;

    if (tid == 0) MBARRIER_INIT(mbar, 1);
    __syncthreads();
    if (tid == 0) {
        MBARRIER_EXPECT_TX(mbar, IMG_BYTES);
        bulk_g2s(sbase, &g_img[f][0], IMG_BYTES, mbar);
    }
    MBARRIER_WAIT_PARITY(mbar, 0);

    const uint32_t bwa  = sbase;
    const uint32_t wgwa = sbase + OFF_WG_B;
    const float*   vecf = (const float*)(smem + OFF_VEC_B);

    float xf[2];
    int   node[2];
    #pragma unroll
    for (int t = 0; t < 2; t++) {
        node[t] = nodeb + g + 8 * t;
        xf[t] = XMIN + (float)node[t] * DX;
    }

    uint32_t a1[4][4];
    #pragma unroll
    for (int s = 0; s < 4; s++) {
        #pragma unroll
        for (int p = 0; p < 2; p++) {
            int u0 = 16 * s + 2 * q + 8 * p;
            float2 wv  = *(const float2*)&vecf[u0];
            float2 bv2 = *(const float2*)&vecf[64 + u0];
            a1[s][2*p]   = packh2(eluf(fmaf(xf[0], wv.x, bv2.x)), eluf(fmaf(xf[0], wv.y, bv2.y)));
            a1[s][2*p+1] = packh2(eluf(fmaf(xf[1], wv.x, bv2.x)), eluf(fmaf(xf[1], wv.y, bv2.y)));
        }
    }

    #pragma unroll
    for (int j = 0; j < 8; j++) {
        uint32_t ad = bwa + (uint32_t)(((8 * j + lrow) * 36 + 4 * lmat) * 4);
        uint32_t bb[8];
        ldsm4(bb, ad);
        ldsm4(bb + 4, ad + 64);
        float c0[4] = {0.f,0.f,0.f,0.f};
        mma16(c0, a1[0], bb[0], bb[1]);
        mma16(c0, a1[1], bb[2], bb[3]);
        mma16(c0, a1[2], bb[4], bb[5]);
        mma16(c0, a1[3], bb[6], bb[7]);
        int cw = 4 * j + q;
        h2u[(g    ) * 36 + cw] = packh2(c0[0], c0[1]);
        h2u[(g + 8) * 36 + cw] = packh2(c0[2], c0[3]);
    }
    __syncwarp();

    uint32_t a2[4][4];
    {
        uint32_t abase = h2a + (uint32_t)((((lmat & 1) * 8 + lrow) * 36 + (lmat >> 1) * 4) * 4);
        #pragma unroll
        for (int s = 0; s < 4; s++)
            ldsm4(a2[s], abase + (uint32_t)(32 * s));
    }

    float sv[2][16];
    float ssum[2] = {0.f, 0.f};
    float ssq[2]  = {0.f, 0.f};
    #pragma unroll 2
    for (int j = 0; j < 8; j++) {
        uint32_t ad1 = wgwa + (uint32_t)(((8 * j + lrow) * 36 + 4 * lmat) * 4);
        uint32_t bb1[8], bb2[8];
        ldsm4(bb1, ad1);
        ldsm4(bb1 + 4, ad1 + 64);
        ldsm4(bb2, ad1 + 9216);
        ldsm4(bb2 + 4, ad1 + 9216 + 64);
        float c1[4] = {0.f,0.f,0.f,0.f};
        float c2[4] = {0.f,0.f,0.f,0.f};
        #pragma unroll
        for (int s = 0; s < 4; s++) {
            mma16(c1, a2[s], bb1[2*s], bb1[2*s+1]);
            mma16(c2, a2[s], bb2[2*s], bb2[2*s+1]);
        }
        int col0 = 8 * j + 2 * q;
        float2 be1v = *(const float2*)&vecf[384 + col0];
        float2 be2v = *(const float2*)&vecf[448 + col0];
        float2 wpv  = *(const float2*)&vecf[128 + col0];
        float2 bpv  = *(const float2*)&vecf[192 + col0];
        #pragma unroll
        for (int t = 0; t < 2; t++) {
            float o1a = c1[2*t]     + be1v.x;
            float o1b = c1[2*t + 1] + be1v.y;
            float o2a = c2[2*t]     + be2v.x;
            float o2b = c2[2*t + 1] + be2v.y;
            float sv0 = fmaf(o1a, sigmf(o2a), fmaf(xf[t], wpv.x, bpv.x));
            float sv1 = fmaf(o1b, sigmf(o2b), fmaf(xf[t], wpv.y, bpv.y));
            sv[t][2*j]     = sv0;
            sv[t][2*j + 1] = sv1;
            ssum[t] += sv0 + sv1;
            ssq[t]  = fmaf(sv0, sv0, fmaf(sv1, sv1, ssq[t]));
        }
    }

    #pragma unroll
    for (int off = 1; off < 4; off <<= 1) {
        #pragma unroll
        for (int t = 0; t < 2; t++) {
            ssum[t] += __shfl_xor_sync(0xffffffffu, ssum[t], off);
            ssq[t]  += __shfl_xor_sync(0xffffffffu, ssq[t],  off);
        }
    }

    #pragma unroll
    for (int t = 0; t < 2; t++) {
        float mean = ssum[t] * (1.f / 64.f);
        float var  = ssq[t] * (1.f / 64.f) - mean * mean;
        float inv  = rsqrtf(var + EPS);
        if (node[t] < NNODE) {
            #pragma unroll
            for (int j = 0; j < 8; j++) {
                int col0 = 8 * j + 2 * q;
                float2 gv = *(const float2*)&vecf[256 + col0];
                float2 bv = *(const float2*)&vecf[320 + col0];
                float y0 = fmaf((sv[t][2*j]     - mean) * inv, gv.x, bv.x);
                float y1 = fmaf((sv[t][2*j + 1] - mean) * inv, gv.y, bv.y);
                g_tab[f][node[t]][4 * j + q] = packh2(y0, y1);
            }
        }
    }
}

// ============================================================================
// Kernel 3: k_fused — phase 1: warps 0-3 compute w (HMMA GRN over F); phase 2:
// all 256 threads table lerp-accumulate.  (R14 version, unchanged)
// ============================================================================
#define KF_W1   0u
#define KF_W2   2560u
#define KF_WG   5120u
#define KF_HT   10240u
#define KF_XT   15360u
#define KF_PRM  24576u
#define KF_WS   25344u
#define KF_SMEM 34560u

__global__ __launch_bounds__(256) void k_fused(
    const float* __restrict__ x,
    const float* __restrict__ w1w, const float* __restrict__ b1w,
    const float* __restrict__ w2w, const float* __restrict__ b2w,
    const float* __restrict__ wg1w, const float* __restrict__ bg1w,
    const float* __restrict__ wg2w, const float* __restrict__ bg2w,
    const float* __restrict__ gammaw, const float* __restrict__ betaw,
    float* __restrict__ wout,
    float* __restrict__ out)
{
    extern __shared__ char smw[];
    __half* w1h = (__half*)(smw + KF_W1);
    __half* w2h = (__half*)(smw + KF_W2);
    __half* wgh = (__half*)(smw + KF_WG);
    float*  xt  = (float*)(smw + KF_XT);
    float*  prm = (float*)(smw + KF_PRM);
    float*  ws  = (float*)(smw + KF_WS);
    const uint32_t sb = smem_u32(smw);

    const int tid  = threadIdx.x;
    const int lane = tid & 31;
    const int warp = tid >> 5;
    const int q    = lane & 3;
    const int g    = lane >> 2;
    const int lrow = lane & 7;
    const int lmat = lane >> 3;
    const size_t blk = (size_t)blockIdx.x * 64;

    for (int i = tid; i < 1024; i += 256) {
        int n = i >> 5, k = i & 31;
        w1h[n * 40 + k] = __float2half_rn(w1w[k * 32 + n]);
        w2h[n * 40 + k] = __float2half_rn(w2w[k * 32 + n]);
    }
    for (int i = tid; i < 2048; i += 256) {
        int n = i >> 5, k = i & 31;
        float v = (n < 32) ? wg1w[k * 32 + n] : wg2w[k * 32 + (n - 32)];
        wgh[n * 40 + k] = __float2half_rn(v);
    }
    if (tid < 32) {
        prm[tid]       = b1w[tid];
        prm[32 + tid]  = b2w[tid];
        prm[64 + tid]  = bg1w[tid];
        prm[96 + tid]  = bg2w[tid];
        prm[128 + tid] = gammaw[tid];
        prm[160 + tid] = betaw[tid];
    }
    {
        const int row = tid >> 2, off = (tid & 3) * 8;
        const float4* xp = (const float4*)(x + (blk + row) * 32 + off);
        float4* xr = (float4*)&xt[row * 36 + off];
        xr[0] = xp[0]; xr[1] = xp[1];
    }
    __syncthreads();

    if (warp < 4) {
        const int wtok = warp * 16;
        uint32_t* h2u = (uint32_t*)(smw + KF_HT) + warp * 320;
        const uint32_t htb = sb + KF_HT + (uint32_t)warp * 1280u;
        const uint32_t abw = htb + (uint32_t)((((lmat & 1) * 8 + lrow) * 20 + (lmat >> 1) * 4) * 4);

        const float* xr0 = &xt[(wtok + g) * 36];
        const float* xr1 = &xt[(wtok + g + 8) * 36];

        uint32_t a1[2][4];
        #pragma unroll
        for (int s = 0; s < 2; s++) {
            int k0 = 16 * s + 2 * q;
            a1[s][0] = packh2(xr0[k0],     xr0[k0 + 1]);
            a1[s][1] = packh2(xr1[k0],     xr1[k0 + 1]);
            a1[s][2] = packh2(xr0[k0 + 8], xr0[k0 + 9]);
            a1[s][3] = packh2(xr1[k0 + 8], xr1[k0 + 9]);
        }

        #pragma unroll
        for (int j = 0; j < 4; j++) {
            uint32_t ad = sb + KF_W1 + (uint32_t)(((8 * j + lrow) * 20 + 4 * lmat) * 4);
            uint32_t bb[4];
            ldsm4(bb, ad);
            float c[4] = {0.f, 0.f, 0.f, 0.f};
            mma16(c, a1[0], bb[0], bb[1]);
            mma16(c, a1[1], bb[2], bb[3]);
            int col0 = 8 * j + 2 * q;
            float b0 = prm[col0], b1v = prm[col0 + 1];
            h2u[g * 20 + 4 * j + q]       = packh2(eluf(c[0] + b0), eluf(c[1] + b1v));
            h2u[(g + 8) * 20 + 4 * j + q] = packh2(eluf(c[2] + b0), eluf(c[3] + b1v));
        }
        __syncwarp();
        uint32_t a2[2][4];
        ldsm4(a2[0], abw);
        ldsm4(a2[1], abw + 32);
        __syncwarp();

        #pragma unroll
        for (int j = 0; j < 4; j++) {
            uint32_t ad = sb + KF_W2 + (uint32_t)(((8 * j + lrow) * 20 + 4 * lmat) * 4);
            uint32_t bb[4];
            ldsm4(bb, ad);
            float c[4] = {0.f, 0.f, 0.f, 0.f};
            mma16(c, a2[0], bb[0], bb[1]);
            mma16(c, a2[1], bb[2], bb[3]);
            int col0 = 8 * j + 2 * q;
            float b0 = prm[32 + col0], b1v = prm[32 + col0 + 1];
            h2u[g * 20 + 4 * j + q]       = packh2(c[0] + b0, c[1] + b1v);
            h2u[(g + 8) * 20 + 4 * j + q] = packh2(c[2] + b0, c[3] + b1v);
        }
        __syncwarp();
        uint32_t a3[2][4];
        ldsm4(a3[0], abw);
        ldsm4(a3[1], abw + 32);

        float o1v[2][8], o2v[2][8];
        #pragma unroll
        for (int j = 0; j < 8; j++) {
            uint32_t ad = sb + KF_WG + (uint32_t)(((8 * j + lrow) * 20 + 4 * lmat) * 4);
            uint32_t bb[4];
            ldsm4(bb, ad);
            float c[4] = {0.f, 0.f, 0.f, 0.f};
            mma16(c, a3[0], bb[0], bb[1]);
            mma16(c, a3[1], bb[2], bb[3]);
            if (j < 4) {
                o1v[0][2*j] = c[0]; o1v[0][2*j+1] = c[1];
                o1v[1][2*j] = c[2]; o1v[1][2*j+1] = c[3];
            } else {
                int jj = j - 4;
                o2v[0][2*jj] = c[0]; o2v[0][2*jj+1] = c[1];
                o2v[1][2*jj] = c[2]; o2v[1][2*jj+1] = c[3];
            }
        }

        float s[2][8];
        float ssum[2] = {0.f, 0.f}, ssq[2] = {0.f, 0.f};
        #pragma unroll
        for (int t = 0; t < 2; t++) {
            const float* xr = (t == 0) ? xr0 : xr1;
            #pragma unroll
            for (int j = 0; j < 4; j++) {
                #pragma unroll
                for (int i2 = 0; i2 < 2; i2++) {
                    int col = 8 * j + 2 * q + i2;
                    float o1 = o1v[t][2*j + i2] + prm[64 + col];
                    float o2 = o2v[t][2*j + i2] + prm[96 + col];
                    float sv = fmaf(o1, sigmf(o2), xr[col]);
                    s[t][2*j + i2] = sv;
                    ssum[t] += sv;
                    ssq[t] = fmaf(sv, sv, ssq[t]);
                }
            }
        }
        #pragma unroll
        for (int off = 1; off < 4; off <<= 1) {
            #pragma unroll
            for (int t = 0; t < 2; t++) {
                ssum[t] += __shfl_xor_sync(0xffffffffu, ssum[t], off);
                ssq[t]  += __shfl_xor_sync(0xffffffffu, ssq[t],  off);
            }
        }
        #pragma unroll
        for (int t = 0; t < 2; t++) {
            float mean = ssum[t] * (1.f / 32.f);
            float var  = ssq[t] * (1.f / 32.f) - mean * mean;
            float inv  = rsqrtf(var + EPS);
            float y[8], mx = -1e30f;
            #pragma unroll
            for (int j = 0; j < 4; j++) {
                #pragma unroll
                for (int i2 = 0; i2 < 2; i2++) {
                    int col = 8 * j + 2 * q + i2;
                    float v = fmaf((s[t][2*j + i2] - mean) * inv, prm[128 + col], prm[160 + col]);
                    y[2*j + i2] = v;
                    mx = fmaxf(mx, v);
                }
            }
            #pragma unroll
            for (int off = 1; off < 4; off <<= 1)
                mx = fmaxf(mx, __shfl_xor_sync(0xffffffffu, mx, off));
            float se = 0.f;
            #pragma unroll
            for (int e = 0; e < 8; e++) { float ev = __expf(y[e] - mx); y[e] = ev; se += ev; }
            #pragma unroll
            for (int off = 1; off < 4; off <<= 1)
                se += __shfl_xor_sync(0xffffffffu, se, off);
            float r = 1.f / se;
            int row = wtok + g + 8 * t;
            float* orow = wout + (blk + row) * (size_t)NF;
            #pragma unroll
            for (int j = 0; j < 4; j++) {
                float2 v2 = make_float2(y[2*j] * r, y[2*j + 1] * r);
                *(float2*)&orow[8 * j + 2 * q] = v2;
                *(float2*)&ws[row * 36 + 8 * j + 2 * q] = v2;
            }
        }
    }
    __syncthreads();

    const int tok = tid >> 2;
    const int ql  = tid & 3;
    const int gb  = ql * 16;

    float acc[16];
    #pragma unroll
    for (int c = 0; c < 16; c++) acc[c] = 0.f;

    #pragma unroll 2
    for (int f = 0; f < NF; f++) {
        float xf = xt[tok * 36 + f];
        float wf = ws[tok * 36 + f];

        float tpos = (xf - XMIN) * INVDX;
        int   i    = (int)tpos;
        i = (i < 0) ? 0 : ((i > NSEG - 1) ? NSEG - 1 : i);
        float fr  = tpos - (float)i;
        float wfr = wf * fr;
        float wfa = wf - wfr;

        const uint4* r0 = (const uint4*)&g_tab[f][i][ql * 8];
        const uint4* r1 = (const uint4*)&g_tab[f][i + 1][ql * 8];
        uint4 a0 = r0[0], a1v = r0[1];
        uint4 b0 = r1[0], b1v = r1[1];

        const uint32_t aw[8] = { a0.x, a0.y, a0.z, a0.w, a1v.x, a1v.y, a1v.z, a1v.w };
        const uint32_t bw[8] = { b0.x, b0.y, b0.z, b0.w, b1v.x, b1v.y, b1v.z, b1v.w };
        #pragma unroll
        for (int c = 0; c < 8; c++) {
            float2 av = unpackh2(aw[c]);
            float2 bv = unpackh2(bw[c]);
            acc[2*c]   = fmaf(av.x, wfa, fmaf(bv.x, wfr, acc[2*c]));
            acc[2*c+1] = fmaf(av.y, wfa, fmaf(bv.y, wfr, acc[2*c+1]));
        }
    }

    {
        float4* op = (float4*)(out + (blk + tok) * NU + gb);
        #pragma unroll
        for (int c = 0; c < 4; c++)
            op[c] = make_float4(acc[4*c], acc[4*c+1], acc[4*c+2], acc[4*c+3]);
    }
}

// ============================================================================
extern "C" void kernel_launch(void* const* d_in, const int* in_sizes, int n_in,
                              void* d_out, int out_size) {
    const float* x    = (const float*)d_in[0];
    const float* W1   = (const float*)d_in[1];
    const float* b1   = (const float*)d_in[2];
    const float* W2   = (const float*)d_in[3];
    const float* b2   = (const float*)d_in[4];
    const float* Wg1  = (const float*)d_in[5];
    const float* bg1  = (const float*)d_in[6];
    const float* Wg2  = (const float*)d_in[7];
    const float* bg2  = (const float*)d_in[8];
    const float* Wp   = (const float*)d_in[9];
    const float* bp   = (const float*)d_in[10];
    const float* gamma= (const float*)d_in[11];
    const float* beta = (const float*)d_in[12];
    const float* w1w  = (const float*)d_in[13];
    const float* b1w  = (const float*)d_in[14];
    const float* w2w  = (const float*)d_in[15];
    const float* b2w  = (const float*)d_in[16];
    const float* wg1w = (const float*)d_in[17];
    const float* bg1w = (const float*)d_in[18];
    const float* wg2w = (const float*)d_in[19];
    const float* bg2w = (const float*)d_in[20];
    const float* gammaw = (const float*)d_in[21];
    const float* betaw  = (const float*)d_in[22];

    float* outp = (float*)d_out;
    float* wp   = outp + W_OFF;

    k_prep<<<NF, 256>>>(W2, Wg1, Wg2, b2, bg1, bg2, W1, b1, Wp, bp, gamma, beta);

    cudaFuncSetAttribute(k_tab, cudaFuncAttributeMaxDynamicSharedMemorySize, KT_SMEM);
    k_tab<<<dim3(7, 32), 256, KT_SMEM>>>();

    cudaFuncSetAttribute(k_fused, cudaFuncAttributeMaxDynamicSharedMemorySize, KF_SMEM);
    k_fused<<<BT / 64, 256, KF_SMEM>>>(
        x, w1w, b1w, w2w, b2w, wg1w, bg1w, wg2w, bg2w, gammaw, betaw, wp, outp);
}

// round 17
// speedup vs baseline: 1.1540x; 1.0641x over previous
#include <cuda_runtime.h>
#include <cuda_fp16.h>
#include <cstdint>

#define BT 32768
#define NF 32
#define NU 64
#define EPS 1e-3f
#define W_OFF (BT * NU)

// ---- GRN-as-1D-function table (post-LN y values) ----
#define XMIN  (-6.0f)
#define NSEG  768
#define DX    0.015625f
#define INVDX 64.0f
#define NNODE 769

// per-feature image (bytes): W2' fp16[64][72] | Wg' fp16[128][72] | vec f32[8][64]
#define IMG_BYTES  29696
#define OFF_WG_B   9216
#define OFF_VEC_B  27648

__device__ __align__(16) unsigned char g_img[NF][IMG_BYTES];
__device__ __align__(16) uint32_t g_tab[NF][NNODE][NU / 2];   // half2-packed y, ~3.15 MB

// ---------------- helpers ----------------
__device__ __forceinline__ uint32_t smem_u32(const void* p) {
    uint32_t a;
    asm("{ .reg .u64 t; cvta.to.shared.u64 t, %1; cvt.u32.u64 %0, t; }" : "=r"(a) : "l"(p));
    return a;
}
__device__ __forceinline__ float eluf(float z)  { return z > 0.f ? z : (__expf(z) - 1.f); }
__device__ __forceinline__ float sigmf(float z) {
    float t, h = 0.5f * z;
    asm("tanh.approx.f32 %0, %1;" : "=f"(t) : "f"(h));
    return fmaf(0.5f, t, 0.5f);
}
__device__ __forceinline__ uint32_t packh2(float lo, float hi) {
    __half2 h = __floats2half2_rn(lo, hi);
    return *reinterpret_cast<uint32_t*>(&h);
}
__device__ __forceinline__ float2 unpackh2(uint32_t u) {
    __half2 h = *reinterpret_cast<__half2*>(&u);
    return __half22float2(h);
}
__device__ __forceinline__ void mma16(float* c, const uint32_t* a, uint32_t b0, uint32_t b1) {
    asm volatile(
        "mma.sync.aligned.m16n8k16.row.col.f32.f16.f16.f32 "
        "{%0,%1,%2,%3}, {%4,%5,%6,%7}, {%8,%9}, {%0,%1,%2,%3};"
        : "+f"(c[0]), "+f"(c[1]), "+f"(c[2]), "+f"(c[3])
        : "r"(a[0]), "r"(a[1]), "r"(a[2]), "r"(a[3]), "r"(b0), "r"(b1));
}
__device__ __forceinline__ void ldsm4(uint32_t* r, uint32_t addr) {
    asm volatile("ldmatrix.sync.aligned.m8n8.x4.shared.b16 {%0,%1,%2,%3}, [%4];"
        : "=r"(r[0]), "=r"(r[1]), "=r"(r[2]), "=r"(r[3]) : "r"(addr));
}

#define MBARRIER_INIT(addr, cnt) \
    asm volatile("mbarrier.init.shared.b64 [%0], %1;" :: "r"(addr), "r"(cnt) : "memory")
#define MBARRIER_EXPECT_TX(addr, tx) \
    asm volatile("mbarrier.arrive.expect_tx.shared.b64 _, [%0], %1;" :: "r"(addr), "r"(tx) : "memory")
#define MBARRIER_WAIT_PARITY(addr, par) do { \
    uint32_t _m = (addr); uint32_t _p = (par); uint32_t _d; \
    asm volatile("{ .reg .pred p; mbarrier.try_wait.parity.acquire.cta.shared::cta.b64 p, [%1], %2; selp.b32 %0, 1, 0, p; }" \
        : "=r"(_d) : "r"(_m), "r"(_p) : "memory"); \
    if (!_d) { \
        asm volatile("{ .reg .pred P1; WL_%=: mbarrier.try_wait.parity.acquire.cta.shared::cta.b64 P1, [%0], %1, 0x989680; @P1 bra.uni WD_%=; bra.uni WL_%=; WD_%=: }" \
            :: "r"(_m), "r"(_p) : "memory"); \
    } } while (0)

__device__ __forceinline__ void bulk_g2s(uint32_t dst, const void* src, uint32_t bytes, uint32_t mbar) {
    asm volatile("cp.async.bulk.shared::cluster.global.mbarrier::complete_tx::bytes [%0], [%1], %2, [%3];"
                 :: "r"(dst), "l"(src), "r"(bytes), "r"(mbar) : "memory");
}

// ============================================================================
// Kernel 1: prep — per-feature fp16 images + folded gate biases.
// Grid 128 = 4 CTAs/feature. COALESCED global reads (source-linear index),
// scattered stores. vec + fold done by part-0 CTA.
// ============================================================================
__global__ __launch_bounds__(256) void k_prep(
    const float* __restrict__ W2, const float* __restrict__ Wg1, const float* __restrict__ Wg2,
    const float* __restrict__ b2, const float* __restrict__ bg1, const float* __restrict__ bg2,
    const float* __restrict__ W1, const float* __restrict__ b1,
    const float* __restrict__ Wp, const float* __restrict__ bp,
    const float* __restrict__ gamma, const float* __restrict__ beta)
{
    __shared__ float b2s[64];
    __shared__ float scr[256];

    const int f    = blockIdx.x >> 2;
    const int part = blockIdx.x & 3;
    const int tid  = threadIdx.x;
    const float* W2f  = W2  + (size_t)f * 4096;
    const float* Wg1f = Wg1 + (size_t)f * 4096;
    const float* Wg2f = Wg2 + (size_t)f * 4096;
    unsigned char* img = g_img[f];
    __half* W2h = (__half*)img;
    __half* Wgh = (__half*)(img + OFF_WG_B);
    float*  vec = (float*)(img + OFF_VEC_B);

    // coalesced reads over this CTA's quarter of each 4096-elem source;
    // i = k*64 + n  (source-linear) -> scattered fp16 stores
    const int i0 = part * 1024;
    #pragma unroll
    for (int i = i0 + tid; i < i0 + 1024; i += 256) {
        int k = i >> 6, n = i & 63;
        W2h[n * 72 + k]        = __float2half_rn(W2f[i]);
        Wgh[n * 72 + k]        = __float2half_rn(Wg1f[i]);
        Wgh[(n + 64) * 72 + k] = __float2half_rn(Wg2f[i]);
    }

    if (part != 0) return;

    if (tid < 64) {
        int o = f * 64 + tid;
        vec[0   + tid] = W1[o];
        vec[64  + tid] = b1[o];
        vec[128 + tid] = Wp[o];
        vec[192 + tid] = bp[o];
        vec[256 + tid] = gamma[o];
        vec[320 + tid] = beta[o];
        b2s[tid] = b2[o];
    }
    __syncthreads();

    // parallel fold: be = bg + b2 @ Wg  (128 outputs x 2-way k-split, coalesced)
    {
        const int o    = tid & 127;
        const int half = tid >> 7;
        const int oo   = o & 63;
        const float* Wsrc = (o < 64) ? Wg1f : Wg2f;
        float s = 0.f;
        #pragma unroll 8
        for (int u = half * 32; u < half * 32 + 32; u++)
            s = fmaf(b2s[u], Wsrc[u * 64 + oo], s);
        scr[tid] = s;
    }
    __syncthreads();
    if (tid < 128) {
        float tot = scr[tid] + scr[tid + 128];
        int oo = tid & 63;
        if (tid < 64) vec[384 + oo] = bg1[f * 64 + oo] + tot;
        else          vec[448 + oo] = bg2[f * 64 + oo] + tot;
    }
}

// ============================================================================
// Kernel 2: k_tab — per-feature GRN at table nodes via HMMA + LN -> fp16 y rows.
// Grid 7 x 32, 256 threads = 8 warps x 16 nodes.
// ============================================================================
#define KT_H2_OFF   29696u
#define KT_MBAR_OFF 48128u
#define KT_SMEM     48144u

__global__ __launch_bounds__(256) void k_tab()
{
    extern __shared__ char smem[];
    const uint32_t sbase = smem_u32(smem);

    const int f    = blockIdx.y;
    const int part = blockIdx.x;
    const int tid  = threadIdx.x;
    const int lane = tid & 31;
    const int warp = tid >> 5;
    const int q    = lane & 3;
    const int g    = lane >> 2;
    const int lrow = lane & 7;
    const int lmat = lane >> 3;
    const int nodeb = part * 128 + warp * 16;

    uint32_t* h2u = (uint32_t*)(smem + KT_H2_OFF) + warp * 576;
    const uint32_t h2a = sbase + KT_H2_OFF + warp * 2304;
    const uint32_t mbar = sbase + KT_MBAR_OFF;

    if (tid == 0) MBARRIER_INIT(mbar, 1);
    __syncthreads();
    if (tid == 0) {
        MBARRIER_EXPECT_TX(mbar, IMG_BYTES);
        bulk_g2s(sbase, &g_img[f][0], IMG_BYTES, mbar);
    }
    MBARRIER_WAIT_PARITY(mbar, 0);

    const uint32_t bwa  = sbase;
    const uint32_t wgwa = sbase + OFF_WG_B;
    const float*   vecf = (const float*)(smem + OFF_VEC_B);

    float xf[2];
    int   node[2];
    #pragma unroll
    for (int t = 0; t < 2; t++) {
        node[t] = nodeb + g + 8 * t;
        xf[t] = XMIN + (float)node[t] * DX;
    }

    uint32_t a1[4][4];
    #pragma unroll
    for (int s = 0; s < 4; s++) {
        #pragma unroll
        for (int p = 0; p < 2; p++) {
            int u0 = 16 * s + 2 * q + 8 * p;
            float2 wv  = *(const float2*)&vecf[u0];
            float2 bv2 = *(const float2*)&vecf[64 + u0];
            a1[s][2*p]   = packh2(eluf(fmaf(xf[0], wv.x, bv2.x)), eluf(fmaf(xf[0], wv.y, bv2.y)));
            a1[s][2*p+1] = packh2(eluf(fmaf(xf[1], wv.x, bv2.x)), eluf(fmaf(xf[1], wv.y, bv2.y)));
        }
    }

    #pragma unroll
    for (int j = 0; j < 8; j++) {
        uint32_t ad = bwa + (uint32_t)(((8 * j + lrow) * 36 + 4 * lmat) * 4);
        uint32_t bb[8];
        ldsm4(bb, ad);
        ldsm4(bb + 4, ad + 64);
        float c0[4] = {0.f,0.f,0.f,0.f};
        mma16(c0, a1[0], bb[0], bb[1]);
        mma16(c0, a1[1], bb[2], bb[3]);
        mma16(c0, a1[2], bb[4], bb[5]);
        mma16(c0, a1[3], bb[6], bb[7]);
        int cw = 4 * j + q;
        h2u[(g    ) * 36 + cw] = packh2(c0[0], c0[1]);
        h2u[(g + 8) * 36 + cw] = packh2(c0[2], c0[3]);
    }
    __syncwarp();

    uint32_t a2[4][4];
    {
        uint32_t abase = h2a + (uint32_t)((((lmat & 1) * 8 + lrow) * 36 + (lmat >> 1) * 4) * 4);
        #pragma unroll
        for (int s = 0; s < 4; s++)
            ldsm4(a2[s], abase + (uint32_t)(32 * s));
    }

    float sv[2][16];
    float ssum[2] = {0.f, 0.f};
    float ssq[2]  = {0.f, 0.f};
    #pragma unroll 2
    for (int j = 0; j < 8; j++) {
        uint32_t ad1 = wgwa + (uint32_t)(((8 * j + lrow) * 36 + 4 * lmat) * 4);
        uint32_t bb1[8], bb2[8];
        ldsm4(bb1, ad1);
        ldsm4(bb1 + 4, ad1 + 64);
        ldsm4(bb2, ad1 + 9216);
        ldsm4(bb2 + 4, ad1 + 9216 + 64);
        float c1[4] = {0.f,0.f,0.f,0.f};
        float c2[4] = {0.f,0.f,0.f,0.f};
        #pragma unroll
        for (int s = 0; s < 4; s++) {
            mma16(c1, a2[s], bb1[2*s], bb1[2*s+1]);
            mma16(c2, a2[s], bb2[2*s], bb2[2*s+1]);
        }
        int col0 = 8 * j + 2 * q;
        float2 be1v = *(const float2*)&vecf[384 + col0];
        float2 be2v = *(const float2*)&vecf[448 + col0];
        float2 wpv  = *(const float2*)&vecf[128 + col0];
        float2 bpv  = *(const float2*)&vecf[192 + col0];
        #pragma unroll
        for (int t = 0; t < 2; t++) {
            float o1a = c1[2*t]     + be1v.x;
            float o1b = c1[2*t + 1] + be1v.y;
            float o2a = c2[2*t]     + be2v.x;
            float o2b = c2[2*t + 1] + be2v.y;
            float sv0 = fmaf(o1a, sigmf(o2a), fmaf(xf[t], wpv.x, bpv.x));
            float sv1 = fmaf(o1b, sigmf(o2b), fmaf(xf[t], wpv.y, bpv.y));
            sv[t][2*j]     = sv0;
            sv[t][2*j + 1] = sv1;
            ssum[t] += sv0 + sv1;
            ssq[t]  = fmaf(sv0, sv0, fmaf(sv1, sv1, ssq[t]));
        }
    }

    #pragma unroll
    for (int off = 1; off < 4; off <<= 1) {
        #pragma unroll
        for (int t = 0; t < 2; t++) {
            ssum[t] += __shfl_xor_sync(0xffffffffu, ssum[t], off);
            ssq[t]  += __shfl_xor_sync(0xffffffffu, ssq[t],  off);
        }
    }

    #pragma unroll
    for (int t = 0; t < 2; t++) {
        float mean = ssum[t] * (1.f / 64.f);
        float var  = ssq[t] * (1.f / 64.f) - mean * mean;
        float inv  = rsqrtf(var + EPS);
        if (node[t] < NNODE) {
            #pragma unroll
            for (int j = 0; j < 8; j++) {
                int col0 = 8 * j + 2 * q;
                float2 gv = *(const float2*)&vecf[256 + col0];
                float2 bv = *(const float2*)&vecf[320 + col0];
                float y0 = fmaf((sv[t][2*j]     - mean) * inv, gv.x, bv.x);
                float y1 = fmaf((sv[t][2*j + 1] - mean) * inv, gv.y, bv.y);
                g_tab[f][node[t]][4 * j + q] = packh2(y0, y1);
            }
        }
    }
}

// ============================================================================
// Kernel 3: k_fused — phase 1: warps 0-3 compute w (HMMA GRN over F); phase 2:
// all 256 threads table lerp-accumulate.
// ============================================================================
#define KF_W1   0u
#define KF_W2   2560u
#define KF_WG   5120u
#define KF_HT   10240u
#define KF_XT   15360u
#define KF_PRM  24576u
#define KF_WS   25344u
#define KF_SMEM 34560u

__global__ __launch_bounds__(256) void k_fused(
    const float* __restrict__ x,
    const float* __restrict__ w1w, const float* __restrict__ b1w,
    const float* __restrict__ w2w, const float* __restrict__ b2w,
    const float* __restrict__ wg1w, const float* __restrict__ bg1w,
    const float* __restrict__ wg2w, const float* __restrict__ bg2w,
    const float* __restrict__ gammaw, const float* __restrict__ betaw,
    float* __restrict__ wout,
    float* __restrict__ out)
{
    extern __shared__ char smw[];
    __half* w1h = (__half*)(smw + KF_W1);
    __half* w2h = (__half*)(smw + KF_W2);
    __half* wgh = (__half*)(smw + KF_WG);
    float*  xt  = (float*)(smw + KF_XT);
    float*  prm = (float*)(smw + KF_PRM);
    float*  ws  = (float*)(smw + KF_WS);
    const uint32_t sb = smem_u32(smw);

    const int tid  = threadIdx.x;
    const int lane = tid & 31;
    const int warp = tid >> 5;
    const int q    = lane & 3;
    const int g    = lane >> 2;
    const int lrow = lane & 7;
    const int lmat = lane >> 3;
    const size_t blk = (size_t)blockIdx.x * 64;

    for (int i = tid; i < 1024; i += 256) {
        int n = i >> 5, k = i & 31;
        w1h[n * 40 + k] = __float2half_rn(w1w[k * 32 + n]);
        w2h[n * 40 + k] = __float2half_rn(w2w[k * 32 + n]);
    }
    for (int i = tid; i < 2048; i += 256) {
        int n = i >> 5, k = i & 31;
        float v = (n < 32) ? wg1w[k * 32 + n] : wg2w[k * 32 + (n - 32)];
        wgh[n * 40 + k] = __float2half_rn(v);
    }
    if (tid < 32) {
        prm[tid]       = b1w[tid];
        prm[32 + tid]  = b2w[tid];
        prm[64 + tid]  = bg1w[tid];
        prm[96 + tid]  = bg2w[tid];
        prm[128 + tid] = gammaw[tid];
        prm[160 + tid] = betaw[tid];
    }
    {
        const int row = tid >> 2, off = (tid & 3) * 8;
        const float4* xp = (const float4*)(x + (blk + row) * 32 + off);
        float4* xr = (float4*)&xt[row * 36 + off];
        xr[0] = xp[0]; xr[1] = xp[1];
    }
    __syncthreads();

    if (warp < 4) {
        const int wtok = warp * 16;
        uint32_t* h2u = (uint32_t*)(smw + KF_HT) + warp * 320;
        const uint32_t htb = sb + KF_HT + (uint32_t)warp * 1280u;
        const uint32_t abw = htb + (uint32_t)((((lmat & 1) * 8 + lrow) * 20 + (lmat >> 1) * 4) * 4);

        const float* xr0 = &xt[(wtok + g) * 36];
        const float* xr1 = &xt[(wtok + g + 8) * 36];

        uint32_t a1[2][4];
        #pragma unroll
        for (int s = 0; s < 2; s++) {
            int k0 = 16 * s + 2 * q;
            a1[s][0] = packh2(xr0[k0],     xr0[k0 + 1]);
            a1[s][1] = packh2(xr1[k0],     xr1[k0 + 1]);
            a1[s][2] = packh2(xr0[k0 + 8], xr0[k0 + 9]);
            a1[s][3] = packh2(xr1[k0 + 8], xr1[k0 + 9]);
        }

        #pragma unroll
        for (int j = 0; j < 4; j++) {
            uint32_t ad = sb + KF_W1 + (uint32_t)(((8 * j + lrow) * 20 + 4 * lmat) * 4);
            uint32_t bb[4];
            ldsm4(bb, ad);
            float c[4] = {0.f, 0.f, 0.f, 0.f};
            mma16(c, a1[0], bb[0], bb[1]);
            mma16(c, a1[1], bb[2], bb[3]);
            int col0 = 8 * j + 2 * q;
            float b0 = prm[col0], b1v = prm[col0 + 1];
            h2u[g * 20 + 4 * j + q]       = packh2(eluf(c[0] + b0), eluf(c[1] + b1v));
            h2u[(g + 8) * 20 + 4 * j + q] = packh2(eluf(c[2] + b0), eluf(c[3] + b1v));
        }
        __syncwarp();
        uint32_t a2[2][4];
        ldsm4(a2[0], abw);
        ldsm4(a2[1], abw + 32);
        __syncwarp();

        #pragma unroll
        for (int j = 0; j < 4; j++) {
            uint32_t ad = sb + KF_W2 + (uint32_t)(((8 * j + lrow) * 20 + 4 * lmat) * 4);
            uint32_t bb[4];
            ldsm4(bb, ad);
            float c[4] = {0.f, 0.f, 0.f, 0.f};
            mma16(c, a2[0], bb[0], bb[1]);
            mma16(c, a2[1], bb[2], bb[3]);
            int col0 = 8 * j + 2 * q;
            float b0 = prm[32 + col0], b1v = prm[32 + col0 + 1];
            h2u[g * 20 + 4 * j + q]       = packh2(c[0] + b0, c[1] + b1v);
            h2u[(g + 8) * 20 + 4 * j + q] = packh2(c[2] + b0, c[3] + b1v);
        }
        __syncwarp();
        uint32_t a3[2][4];
        ldsm4(a3[0], abw);
        ldsm4(a3[1], abw + 32);

        float o1v[2][8], o2v[2][8];
        #pragma unroll
        for (int j = 0; j < 8; j++) {
            uint32_t ad = sb + KF_WG + (uint32_t)(((8 * j + lrow) * 20 + 4 * lmat) * 4);
            uint32_t bb[4];
            ldsm4(bb, ad);
            float c[4] = {0.f, 0.f, 0.f, 0.f};
            mma16(c, a3[0], bb[0], bb[1]);
            mma16(c, a3[1], bb[2], bb[3]);
            if (j < 4) {
                o1v[0][2*j] = c[0]; o1v[0][2*j+1] = c[1];
                o1v[1][2*j] = c[2]; o1v[1][2*j+1] = c[3];
            } else {
                int jj = j - 4;
                o2v[0][2*jj] = c[0]; o2v[0][2*jj+1] = c[1];
                o2v[1][2*jj] = c[2]; o2v[1][2*jj+1] = c[3];
            }
        }

        float s[2][8];
        float ssum[2] = {0.f, 0.f}, ssq[2] = {0.f, 0.f};
        #pragma unroll
        for (int t = 0; t < 2; t++) {
            const float* xr = (t == 0) ? xr0 : xr1;
            #pragma unroll
            for (int j = 0; j < 4; j++) {
                #pragma unroll
                for (int i2 = 0; i2 < 2; i2++) {
                    int col = 8 * j + 2 * q + i2;
                    float o1 = o1v[t][2*j + i2] + prm[64 + col];
                    float o2 = o2v[t][2*j + i2] + prm[96 + col];
                    float sv = fmaf(o1, sigmf(o2), xr[col]);
                    s[t][2*j + i2] = sv;
                    ssum[t] += sv;
                    ssq[t] = fmaf(sv, sv, ssq[t]);
                }
            }
        }
        #pragma unroll
        for (int off = 1; off < 4; off <<= 1) {
            #pragma unroll
            for (int t = 0; t < 2; t++) {
                ssum[t] += __shfl_xor_sync(0xffffffffu, ssum[t], off);
                ssq[t]  += __shfl_xor_sync(0xffffffffu, ssq[t],  off);
            }
        }
        #pragma unroll
        for (int t = 0; t < 2; t++) {
            float mean = ssum[t] * (1.f / 32.f);
            float var  = ssq[t] * (1.f / 32.f) - mean * mean;
            float inv  = rsqrtf(var + EPS);
            float y[8], mx = -1e30f;
            #pragma unroll
            for (int j = 0; j < 4; j++) {
                #pragma unroll
                for (int i2 = 0; i2 < 2; i2++) {
                    int col = 8 * j + 2 * q + i2;
                    float v = fmaf((s[t][2*j + i2] - mean) * inv, prm[128 + col], prm[160 + col]);
                    y[2*j + i2] = v;
                    mx = fmaxf(mx, v);
                }
            }
            #pragma unroll
            for (int off = 1; off < 4; off <<= 1)
                mx = fmaxf(mx, __shfl_xor_sync(0xffffffffu, mx, off));
            float se = 0.f;
            #pragma unroll
            for (int e = 0; e < 8; e++) { float ev = __expf(y[e] - mx); y[e] = ev; se += ev; }
            #pragma unroll
            for (int off = 1; off < 4; off <<= 1)
                se += __shfl_xor_sync(0xffffffffu, se, off);
            float r = 1.f / se;
            int row = wtok + g + 8 * t;
            float* orow = wout + (blk + row) * (size_t)NF;
            #pragma unroll
            for (int j = 0; j < 4; j++) {
                float2 v2 = make_float2(y[2*j] * r, y[2*j + 1] * r);
                *(float2*)&orow[8 * j + 2 * q] = v2;
                *(float2*)&ws[row * 36 + 8 * j + 2 * q] = v2;
            }
        }
    }
    __syncthreads();

    const int tok = tid >> 2;
    const int ql  = tid & 3;
    const int gb  = ql * 16;

    float acc[16];
    #pragma unroll
    for (int c = 0; c < 16; c++) acc[c] = 0.f;

    #pragma unroll 2
    for (int f = 0; f < NF; f++) {
        float xf = xt[tok * 36 + f];
        float wf = ws[tok * 36 + f];

        float tpos = (xf - XMIN) * INVDX;
        int   i    = (int)tpos;
        i = (i < 0) ? 0 : ((i > NSEG - 1) ? NSEG - 1 : i);
        float fr  = tpos - (float)i;
        float wfr = wf * fr;
        float wfa = wf - wfr;

        const uint4* r0 = (const uint4*)&g_tab[f][i][ql * 8];
        const uint4* r1 = (const uint4*)&g_tab[f][i + 1][ql * 8];
        uint4 a0 = r0[0], a1v = r0[1];
        uint4 b0 = r1[0], b1v = r1[1];

        const uint32_t aw[8] = { a0.x, a0.y, a0.z, a0.w, a1v.x, a1v.y, a1v.z, a1v.w };
        const uint32_t bw[8] = { b0.x, b0.y, b0.z, b0.w, b1v.x, b1v.y, b1v.z, b1v.w };
        #pragma unroll
        for (int c = 0; c < 8; c++) {
            float2 av = unpackh2(aw[c]);
            float2 bv = unpackh2(bw[c]);
            acc[2*c]   = fmaf(av.x, wfa, fmaf(bv.x, wfr, acc[2*c]));
            acc[2*c+1] = fmaf(av.y, wfa, fmaf(bv.y, wfr, acc[2*c+1]));
        }
    }

    {
        float4* op = (float4*)(out + (blk + tok) * NU + gb);
        #pragma unroll
        for (int c = 0; c < 4; c++)
            op[c] = make_float4(acc[4*c], acc[4*c+1], acc[4*c+2], acc[4*c+3]);
    }
}

// ============================================================================
extern "C" void kernel_launch(void* const* d_in, const int* in_sizes, int n_in,
                              void* d_out, int out_size) {
    const float* x    = (const float*)d_in[0];
    const float* W1   = (const float*)d_in[1];
    const float* b1   = (const float*)d_in[2];
    const float* W2   = (const float*)d_in[3];
    const float* b2   = (const float*)d_in[4];
    const float* Wg1  = (const float*)d_in[5];
    const float* bg1  = (const float*)d_in[6];
    const float* Wg2  = (const float*)d_in[7];
    const float* bg2  = (const float*)d_in[8];
    const float* Wp   = (const float*)d_in[9];
    const float* bp   = (const float*)d_in[10];
    const float* gamma= (const float*)d_in[11];
    const float* beta = (const float*)d_in[12];
    const float* w1w  = (const float*)d_in[13];
    const float* b1w  = (const float*)d_in[14];
    const float* w2w  = (const float*)d_in[15];
    const float* b2w  = (const float*)d_in[16];
    const float* wg1w = (const float*)d_in[17];
    const float* bg1w = (const float*)d_in[18];
    const float* wg2w = (const float*)d_in[19];
    const float* bg2w = (const float*)d_in[20];
    const float* gammaw = (const float*)d_in[21];
    const float* betaw  = (const float*)d_in[22];

    float* outp = (float*)d_out;
    float* wp   = outp + W_OFF;

    k_prep<<<NF * 4, 256>>>(W2, Wg1, Wg2, b2, bg1, bg2, W1, b1, Wp, bp, gamma, beta);

    cudaFuncSetAttribute(k_tab, cudaFuncAttributeMaxDynamicSharedMemorySize, KT_SMEM);
    k_tab<<<dim3(7, 32), 256, KT_SMEM>>>();

    cudaFuncSetAttribute(k_fused, cudaFuncAttributeMaxDynamicSharedMemorySize, KF_SMEM);
    k_fused<<<BT / 64, 256, KF_SMEM>>>(
        x, w1w, b1w, w2w, b2w, wg1w, bg1w, wg2w, bg2w, gammaw, betaw, wp, outp);
}